// round 16
// baseline (speedup 1.0000x reference)
#include <cuda_runtime.h>

// Trilinear interpolation:
//   img:    [64, 64, 64, 64]  (D, H, W, C) fp32, C contiguous
//   coords: [200000, 3] fp32 in [0, 128)  -> scaled by 1/2 into [0, 64)
//   out:    [200000, 64] fp32
//
// Half-warp per point (lanes 0-15 -> pt 2w, lanes 16-31 -> pt 2w+1), each
// lane owns 4 channels. 8 corner LDG.128 front-batched; accumulation uses
// Blackwell packed fma.rn.f32x2 (2 FFMA2 per corner instead of 4 FFMA).
// __launch_bounds__(256,6) -> 42-reg budget: ~6 loads genuinely in flight
// at 48 warps/SM (R14's (256,8) forced 32 regs and serialized the batch).

#define GRID_H   64
#define CHANNELS 64

__device__ __forceinline__ unsigned long long pack2(float lo, float hi) {
    unsigned long long r;
    asm("mov.b64 %0, {%1, %2};" : "=l"(r) : "f"(lo), "f"(hi));
    return r;
}
__device__ __forceinline__ void unpack2(unsigned long long v, float& lo, float& hi) {
    asm("mov.b64 {%0, %1}, %2;" : "=f"(lo), "=f"(hi) : "l"(v));
}
__device__ __forceinline__ unsigned long long mul2(unsigned long long a,
                                                   unsigned long long b) {
    unsigned long long d;
    asm("mul.rn.f32x2 %0, %1, %2;" : "=l"(d) : "l"(a), "l"(b));
    return d;
}
__device__ __forceinline__ unsigned long long fma2(unsigned long long a,
                                                   unsigned long long b,
                                                   unsigned long long c) {
    unsigned long long d;
    asm("fma.rn.f32x2 %0, %1, %2, %3;" : "=l"(d) : "l"(a), "l"(b), "l"(c));
    return d;
}

__global__ __launch_bounds__(256, 6)
void proj_trilerp_kernel(const float* __restrict__ img,
                         const float* __restrict__ coords,
                         float* __restrict__ out,
                         int npts)
{
    const int warp = (blockIdx.x * blockDim.x + threadIdx.x) >> 5;
    const int lane = threadIdx.x & 31;
    const int pt   = warp * 2 + (lane >> 4);   // this half-warp's point
    if (pt >= npts) return;

    // Broadcast within each half-warp (2 sectors per load instruction)
    const float x = __ldg(&coords[pt * 3 + 0]) * 0.5f;  // factor = 128/64 = 2
    const float y = __ldg(&coords[pt * 3 + 1]) * 0.5f;
    const float z = __ldg(&coords[pt * 3 + 2]) * 0.5f;

    const float hm1 = (float)(GRID_H - 1);
    const float x1f = floorf(x), x2f = fminf(ceilf(x), hm1);
    const float y1f = floorf(y), y2f = fminf(ceilf(y), hm1);
    const float z1f = floorf(z), z2f = fminf(ceilf(z), hm1);

    // Reference weights: low corner gets (hi - p), high corner gets (p - lo).
    // Degenerate lo==hi: both weights sum to 0, matching the reference.
    const float cx1 = x - x1f, cx0 = x2f - x;
    const float cy1 = y - y1f, cy0 = y2f - y;
    const float cz1 = z - z1f, cz0 = z2f - z;

    const int bx1 = (int)x1f * (GRID_H * GRID_H * CHANNELS);
    const int bx2 = (int)x2f * (GRID_H * GRID_H * CHANNELS);
    const int by1 = (int)y1f * (GRID_H * CHANNELS);
    const int by2 = (int)y2f * (GRID_H * CHANNELS);
    const int bz1 = (int)z1f * CHANNELS;
    const int bz2 = (int)z2f * CHANNELS;

    const int c = (lane & 15) * 4;   // this lane's 4 channels (16B)

    const ulonglong2* p000 = (const ulonglong2*)(img + bx1 + by1 + bz1 + c);
    const ulonglong2* p100 = (const ulonglong2*)(img + bx2 + by1 + bz1 + c);
    const ulonglong2* p010 = (const ulonglong2*)(img + bx1 + by2 + bz1 + c);
    const ulonglong2* p110 = (const ulonglong2*)(img + bx2 + by2 + bz1 + c);
    const ulonglong2* p001 = (const ulonglong2*)(img + bx1 + by1 + bz2 + c);
    const ulonglong2* p101 = (const ulonglong2*)(img + bx2 + by1 + bz2 + c);
    const ulonglong2* p011 = (const ulonglong2*)(img + bx1 + by2 + bz2 + c);
    const ulonglong2* p111 = (const ulonglong2*)(img + bx2 + by2 + bz2 + c);

    // Front-batch the wide loads (as deep as the 42-reg budget allows)
    const ulonglong2 q000 = *p000;
    const ulonglong2 q100 = *p100;
    const ulonglong2 q010 = *p010;
    const ulonglong2 q110 = *p110;
    const ulonglong2 q001 = *p001;
    const ulonglong2 q101 = *p101;
    const ulonglong2 q011 = *p011;
    const ulonglong2 q111 = *p111;

    // Packed trilinear weights {w, w}
    const unsigned long long w000 = pack2(cx0 * cy0 * cz0, cx0 * cy0 * cz0);
    const unsigned long long w100 = pack2(cx1 * cy0 * cz0, cx1 * cy0 * cz0);
    const unsigned long long w010 = pack2(cx0 * cy1 * cz0, cx0 * cy1 * cz0);
    const unsigned long long w110 = pack2(cx1 * cy1 * cz0, cx1 * cy1 * cz0);
    const unsigned long long w001 = pack2(cx0 * cy0 * cz1, cx0 * cy0 * cz1);
    const unsigned long long w101 = pack2(cx1 * cy0 * cz1, cx1 * cy0 * cz1);
    const unsigned long long w011 = pack2(cx0 * cy1 * cz1, cx0 * cy1 * cz1);
    const unsigned long long w111 = pack2(cx1 * cy1 * cz1, cx1 * cy1 * cz1);

    // 2 FFMA2 per corner: acc01 = channels {c, c+1}, acc23 = {c+2, c+3}
    unsigned long long a01 = mul2(w000, q000.x);
    unsigned long long a23 = mul2(w000, q000.y);
    a01 = fma2(w100, q100.x, a01);  a23 = fma2(w100, q100.y, a23);
    a01 = fma2(w010, q010.x, a01);  a23 = fma2(w010, q010.y, a23);
    a01 = fma2(w110, q110.x, a01);  a23 = fma2(w110, q110.y, a23);
    a01 = fma2(w001, q001.x, a01);  a23 = fma2(w001, q001.y, a23);
    a01 = fma2(w101, q101.x, a01);  a23 = fma2(w101, q101.y, a23);
    a01 = fma2(w011, q011.x, a01);  a23 = fma2(w011, q011.y, a23);
    a01 = fma2(w111, q111.x, a01);  a23 = fma2(w111, q111.y, a23);

    float4 r;
    unpack2(a01, r.x, r.y);
    unpack2(a23, r.z, r.w);

    // Streaming store: output is write-once; don't evict the volume from L2.
    __stcs((float4*)(out + pt * CHANNELS + c), r);
}

extern "C" void kernel_launch(void* const* d_in, const int* in_sizes, int n_in,
                              void* d_out, int out_size)
{
    const float* img    = (const float*)d_in[0];   // [1,64,64,64,64]
    const float* coords = (const float*)d_in[1];   // [1,200000,3]
    float* out          = (float*)d_out;           // [1,200000,64]

    const int npts = in_sizes[1] / 3;              // 200000

    // 2 points per warp, 8 warps per block -> 16 points per block
    const int pts_per_block = 16;
    const int blocks = (npts + pts_per_block - 1) / pts_per_block;
    proj_trilerp_kernel<<<blocks, 256>>>(img, coords, out, npts);
}

// round 17
// speedup vs baseline: 1.0138x; 1.0138x over previous
#include <cuda_runtime.h>

// Trilinear interpolation:
//   img:    [64, 64, 64, 64]  (D, H, W, C) fp32, C contiguous
//   coords: [200000, 3] fp32 in [0, 128)  -> scaled by 1/2 into [0, 64)
//   out:    [200000, 64] fp32
//
// R14 structure (proven best: 32 regs, 64 warps/SM, half-warp per point,
// 8 front-batched LDG.128 per point) + L2 residency control:
//   - volume loads carry an L2::evict_last cache-hint policy, so the 64MB
//     volume (< 126MB L2) stays L2-resident across graph replays instead of
//     being re-fetched from DRAM every launch;
//   - output stores stay streaming (__stcs) so the 51MB write stream does
//     not evict the volume.

#define GRID_H   64
#define CHANNELS 64

// float4 global load with L2 evict_last cache-hint.
__device__ __forceinline__ float4 ldg_keep(const float4* p, unsigned long long pol)
{
    float4 v;
    asm("ld.global.nc.L2::cache_hint.v4.f32 {%0,%1,%2,%3}, [%4], %5;"
        : "=f"(v.x), "=f"(v.y), "=f"(v.z), "=f"(v.w)
        : "l"(p), "l"(pol));
    return v;
}

__global__ __launch_bounds__(256, 8)
void proj_trilerp_kernel(const float* __restrict__ img,
                         const float* __restrict__ coords,
                         float* __restrict__ out,
                         int npts)
{
    const int warp = (blockIdx.x * blockDim.x + threadIdx.x) >> 5;
    const int lane = threadIdx.x & 31;
    const int pt   = warp * 2 + (lane >> 4);   // this half-warp's point
    if (pt >= npts) return;

    // L2 evict_last policy for the feature volume (uniform -> U-pipe, cheap)
    unsigned long long pol;
    asm("createpolicy.fractional.L2::evict_last.b64 %0, 1.0;" : "=l"(pol));

    // Broadcast within each half-warp (2 sectors per load instruction)
    const float x = __ldg(&coords[pt * 3 + 0]) * 0.5f;  // factor = 128/64 = 2
    const float y = __ldg(&coords[pt * 3 + 1]) * 0.5f;
    const float z = __ldg(&coords[pt * 3 + 2]) * 0.5f;

    const float hm1 = (float)(GRID_H - 1);
    const float x1f = floorf(x), x2f = fminf(ceilf(x), hm1);
    const float y1f = floorf(y), y2f = fminf(ceilf(y), hm1);
    const float z1f = floorf(z), z2f = fminf(ceilf(z), hm1);

    // Reference weights: low corner gets (hi - p), high corner gets (p - lo).
    // Degenerate lo==hi: both weights sum to 0, matching the reference.
    const float cx1 = x - x1f, cx0 = x2f - x;
    const float cy1 = y - y1f, cy0 = y2f - y;
    const float cz1 = z - z1f, cz0 = z2f - z;

    const int bx1 = (int)x1f * (GRID_H * GRID_H * CHANNELS);
    const int bx2 = (int)x2f * (GRID_H * GRID_H * CHANNELS);
    const int by1 = (int)y1f * (GRID_H * CHANNELS);
    const int by2 = (int)y2f * (GRID_H * CHANNELS);
    const int bz1 = (int)z1f * CHANNELS;
    const int bz2 = (int)z2f * CHANNELS;

    const int c = (lane & 15) * 4;   // this lane's 4 channels (16B)

    const float4* p000 = (const float4*)(img + bx1 + by1 + bz1 + c);
    const float4* p100 = (const float4*)(img + bx2 + by1 + bz1 + c);
    const float4* p010 = (const float4*)(img + bx1 + by2 + bz1 + c);
    const float4* p110 = (const float4*)(img + bx2 + by2 + bz1 + c);
    const float4* p001 = (const float4*)(img + bx1 + by1 + bz2 + c);
    const float4* p101 = (const float4*)(img + bx2 + by1 + bz2 + c);
    const float4* p011 = (const float4*)(img + bx1 + by2 + bz2 + c);
    const float4* p111 = (const float4*)(img + bx2 + by2 + bz2 + c);

    // Front-batch all 8 wide loads (as deep as the 32-reg budget allows)
    const float4 q000 = ldg_keep(p000, pol);
    const float4 q100 = ldg_keep(p100, pol);
    const float4 q010 = ldg_keep(p010, pol);
    const float4 q110 = ldg_keep(p110, pol);
    const float4 q001 = ldg_keep(p001, pol);
    const float4 q101 = ldg_keep(p101, pol);
    const float4 q011 = ldg_keep(p011, pol);
    const float4 q111 = ldg_keep(p111, pol);

    // 8 trilinear weights
    const float w000 = cx0 * cy0 * cz0;
    const float w100 = cx1 * cy0 * cz0;
    const float w010 = cx0 * cy1 * cz0;
    const float w110 = cx1 * cy1 * cz0;
    const float w001 = cx0 * cy0 * cz1;
    const float w101 = cx1 * cy0 * cz1;
    const float w011 = cx0 * cy1 * cz1;
    const float w111 = cx1 * cy1 * cz1;

    float ax, ay, az, aw;
    ax = w000 * q000.x;            ay = w000 * q000.y;
    az = w000 * q000.z;            aw = w000 * q000.w;
    ax = fmaf(w100, q100.x, ax);   ay = fmaf(w100, q100.y, ay);
    az = fmaf(w100, q100.z, az);   aw = fmaf(w100, q100.w, aw);
    ax = fmaf(w010, q010.x, ax);   ay = fmaf(w010, q010.y, ay);
    az = fmaf(w010, q010.z, az);   aw = fmaf(w010, q010.w, aw);
    ax = fmaf(w110, q110.x, ax);   ay = fmaf(w110, q110.y, ay);
    az = fmaf(w110, q110.z, az);   aw = fmaf(w110, q110.w, aw);
    ax = fmaf(w001, q001.x, ax);   ay = fmaf(w001, q001.y, ay);
    az = fmaf(w001, q001.z, az);   aw = fmaf(w001, q001.w, aw);
    ax = fmaf(w101, q101.x, ax);   ay = fmaf(w101, q101.y, ay);
    az = fmaf(w101, q101.z, az);   aw = fmaf(w101, q101.w, aw);
    ax = fmaf(w011, q011.x, ax);   ay = fmaf(w011, q011.y, ay);
    az = fmaf(w011, q011.z, az);   aw = fmaf(w011, q011.w, aw);
    ax = fmaf(w111, q111.x, ax);   ay = fmaf(w111, q111.y, ay);
    az = fmaf(w111, q111.z, az);   aw = fmaf(w111, q111.w, aw);

    // Streaming store: output is write-once; don't evict the volume from L2.
    __stcs((float4*)(out + pt * CHANNELS + c), make_float4(ax, ay, az, aw));
}

extern "C" void kernel_launch(void* const* d_in, const int* in_sizes, int n_in,
                              void* d_out, int out_size)
{
    const float* img    = (const float*)d_in[0];   // [1,64,64,64,64]
    const float* coords = (const float*)d_in[1];   // [1,200000,3]
    float* out          = (float*)d_out;           // [1,200000,64]

    const int npts = in_sizes[1] / 3;              // 200000

    // 2 points per warp, 8 warps per block -> 16 points per block
    const int pts_per_block = 16;
    const int blocks = (npts + pts_per_block - 1) / pts_per_block;
    proj_trilerp_kernel<<<blocks, 256>>>(img, coords, out, npts);
}